// round 4
// baseline (speedup 1.0000x reference)
#include <cuda_runtime.h>
#include <cuda_fp16.h>
#include <mma.h>
#include <cstdint>

using namespace nvcuda;

// Problem dims (fixed)
#define Td  4
#define Bd  32
#define Cd  512
#define CVd 2048
#define Nd  256
#define NHd 8
#define DHd 64
#define DVd 256
#define TBd (Td*Bd)      // 128
#define Zd  (TBd*NHd)    // 1024

// ---------------- static scratch ------------------------------------------------
__device__ __half g_xs [(size_t)TBd*Cd *Nd];    // x spikes (fp16, exact)
__device__ __half g_qh [(size_t)TBd*Cd *Nd];    // q/k/v spikes (fp16, exact)
__device__ __half g_kh [(size_t)TBd*Cd *Nd];
__device__ __half g_vh [(size_t)TBd*CVd*Nd];
__device__ __half g_kvhi[(size_t)Zd*DHd*DVd];   // lossless hi/lo split of K V^T
__device__ __half g_kvlo[(size_t)Zd*DHd*DVd];
__device__ __half g_oh [(size_t)TBd*CVd*Nd];    // attn spikes (fp16, exact)
// folded weights (scale folded in), split hi/lo
__device__ __half g_wq_hi[Cd*Cd],  g_wq_lo[Cd*Cd];
__device__ __half g_wk_hi[Cd*Cd],  g_wk_lo[Cd*Cd];
__device__ __half g_wv_hi[CVd*Cd], g_wv_lo[CVd*Cd];
__device__ __half g_wp_hi[Cd*CVd], g_wp_lo[Cd*CVd];

// ---------------- prep: fold BN scale into weights, split hi/lo ------------------
__global__ void prep_w(const float* __restrict__ w, const float* __restrict__ scale,
                       __half* __restrict__ hi, __half* __restrict__ lo, int M, int K)
{
    int i = blockIdx.x * blockDim.x + threadIdx.x;
    if (i >= M * K) return;
    float v = w[i] * scale[i / K];
    __half h = __float2half_rn(v);
    hi[i] = h;
    lo[i] = __float2half_rn(v - __half2float(h));
}

// ---------------- SFA scan on input x: fp32 -> fp16 spikes ----------------------
__global__ void sfa_f2h(const float* __restrict__ in, __half* __restrict__ out, int perT)
{
    int i = blockIdx.x * blockDim.x + threadIdx.x;
    if (i >= perT) return;
    float h = 0.f;
#pragma unroll
    for (int t = 0; t < Td; ++t) {
        float u = h + in[(size_t)t * perT + i];
        float s = rintf(fminf(fmaxf(u, 0.f), 8.f));   // round-half-to-even
        h = u - s;
        out[(size_t)t * perT + i] = __float2half_rn(s * 0.125f);
    }
}

// ---------------- fused conv GEMM + bias + (optional) SFA epilogue ---------------
// For fixed b (blockIdx.z): loop t=0..3, Y_t = (Whi+Wlo)[M,K] @ X_t[K,Nd] + bias.
// If SFA: carry membrane h across t in registers, emit fp16 spikes.
// Block tile 128(M) x 64(N), BK=32, 8 warps (4x2), warp tile 32x32.
// Stage stride 36 floats (144 B, multiple of 16 B as WMMA requires).
static constexpr int SM_AH = 0;                        // 128*40 halves = 10240 B
static constexpr int SM_AL = 10240;                    // 10240 B
static constexpr int SM_B  = 20480;                    // 32*72 halves  = 4608 B
static constexpr int SM_SZ = 8 * 32 * 36 * 4;          // 36864 B stage (unions tiles)

template<bool SFA>
__global__ void __launch_bounds__(256)
conv_fused(const __half* __restrict__ Ahi, const __half* __restrict__ Alo,
           const __half* __restrict__ Ball, const float* __restrict__ bias,
           void* __restrict__ Yout, int M, int K)
{
    __shared__ __align__(16) unsigned char smraw[SM_SZ];
    __half (*sAh)[40] = (__half(*)[40])(smraw + SM_AH);
    __half (*sAl)[40] = (__half(*)[40])(smraw + SM_AL);
    __half (*sB )[72] = (__half(*)[72])(smraw + SM_B);

    const int tid  = threadIdx.x;
    const int warp = tid >> 5, lane = tid & 31;
    const int wy = warp >> 1, wx = warp & 1;
    const int mBase = blockIdx.y * 128, nBase = blockIdx.x * 64;
    const int bz = blockIdx.z;

    float* st = (float*)smraw + warp * (32 * 36);

    const int ar = tid >> 1, ac = (tid & 1) * 16;   // A loader: 128 rows x 32 k
    const int br = tid >> 3, bc = (tid & 7) * 8;    // B loader: 32 k x 64 n

    const int mRow = mBase + wy * 32 + lane;
    const float bi = bias[mRow];

    float hreg[32];
    if (SFA) {
#pragma unroll
        for (int c = 0; c < 32; ++c) hreg[c] = 0.f;
    }

    for (int t = 0; t < Td; ++t) {
        const __half* B = Ball + (size_t)(t * Bd + bz) * K * Nd;

        wmma::fragment<wmma::accumulator, 16, 16, 16, float> acc[2][2];
#pragma unroll
        for (int i = 0; i < 2; ++i)
#pragma unroll
            for (int j = 0; j < 2; ++j) wmma::fill_fragment(acc[i][j], 0.f);

        for (int kb = 0; kb < K; kb += 32) {
            *(uint4*)&sAh[ar][ac    ] = *(const uint4*)&Ahi[(size_t)(mBase + ar) * K + kb + ac];
            *(uint4*)&sAh[ar][ac + 8] = *(const uint4*)&Ahi[(size_t)(mBase + ar) * K + kb + ac + 8];
            *(uint4*)&sAl[ar][ac    ] = *(const uint4*)&Alo[(size_t)(mBase + ar) * K + kb + ac];
            *(uint4*)&sAl[ar][ac + 8] = *(const uint4*)&Alo[(size_t)(mBase + ar) * K + kb + ac + 8];
            *(uint4*)&sB [br][bc    ] = *(const uint4*)&B  [(size_t)(kb + br) * Nd + nBase + bc];
            __syncthreads();
#pragma unroll
            for (int kk = 0; kk < 32; kk += 16) {
                wmma::fragment<wmma::matrix_a, 16, 16, 16, half, wmma::row_major> ah[2], al[2];
#pragma unroll
                for (int i = 0; i < 2; ++i) {
                    wmma::load_matrix_sync(ah[i], &sAh[wy * 32 + i * 16][kk], 40);
                    wmma::load_matrix_sync(al[i], &sAl[wy * 32 + i * 16][kk], 40);
                }
#pragma unroll
                for (int j = 0; j < 2; ++j) {
                    wmma::fragment<wmma::matrix_b, 16, 16, 16, half, wmma::row_major> bf;
                    wmma::load_matrix_sync(bf, &sB[kk][wx * 32 + j * 16], 72);
#pragma unroll
                    for (int i = 0; i < 2; ++i) {
                        wmma::mma_sync(acc[i][j], ah[i], bf, acc[i][j]);
                        wmma::mma_sync(acc[i][j], al[i], bf, acc[i][j]);
                    }
                }
            }
            __syncthreads();
        }

        // epilogue: stage warp tile 32x32 -> smem (ldm=36), lane owns one row
#pragma unroll
        for (int i = 0; i < 2; ++i)
#pragma unroll
            for (int j = 0; j < 2; ++j)
                wmma::store_matrix_sync(st + (i * 16) * 36 + j * 16, acc[i][j], 36,
                                        wmma::mem_row_major);
        __syncwarp();

        if (SFA) {
            __align__(16) __half tmp[32];
#pragma unroll
            for (int c = 0; c < 32; ++c) {
                float u = hreg[c] + st[lane * 36 + c] + bi;
                float s = rintf(fminf(fmaxf(u, 0.f), 8.f));
                hreg[c] = u - s;
                tmp[c] = __float2half_rn(s * 0.125f);
            }
            __half* yp = ((__half*)Yout) + ((size_t)(t * Bd + bz) * M + mRow) * Nd
                         + nBase + wx * 32;
#pragma unroll
            for (int c = 0; c < 4; ++c) ((uint4*)yp)[c] = ((const uint4*)tmp)[c];
        } else {
            __align__(16) float tmp[32];
#pragma unroll
            for (int c = 0; c < 32; ++c) tmp[c] = st[lane * 36 + c] + bi;
            float* yp = ((float*)Yout) + ((size_t)(t * Bd + bz) * M + mRow) * Nd
                        + nBase + wx * 32;
#pragma unroll
            for (int c = 0; c < 8; ++c) ((float4*)yp)[c] = ((const float4*)tmp)[c];
        }
        __syncthreads();   // stage region overlaps tiles; protect next t's loads
    }
}

// ---------------- kv = K V^T with fused lossless hi/lo split --------------------
// One block per z = tb*8+h. 8 warps (4x2), warp tile 16(D) x 128(E).
__global__ void __launch_bounds__(256)
kv_wmma()
{
    __shared__ __align__(16) float stg[8][16 * 68];   // per-warp 16x68 chunk stage

    const int tid = threadIdx.x, warp = tid >> 5, lane = tid & 31;
    const int wy = warp >> 1, wx = warp & 1;
    const int z = blockIdx.x;
    const int tb = z >> 3, h = z & 7;

    const __half* Kp = g_kh + ((size_t)tb * Cd  + h * DHd) * Nd;
    const __half* Vp = g_vh + ((size_t)tb * CVd + h * DVd) * Nd;
    __half* KVh = g_kvhi + (size_t)z * DHd * DVd;
    __half* KVl = g_kvlo + (size_t)z * DHd * DVd;

    wmma::fragment<wmma::accumulator, 16, 16, 16, float> acc[8];
#pragma unroll
    for (int j = 0; j < 8; ++j) wmma::fill_fragment(acc[j], 0.f);

    for (int k0 = 0; k0 < Nd; k0 += 16) {
        wmma::fragment<wmma::matrix_a, 16, 16, 16, half, wmma::row_major> a;
        wmma::load_matrix_sync(a, Kp + (size_t)(wy * 16) * Nd + k0, Nd);
#pragma unroll
        for (int j = 0; j < 8; ++j) {
            wmma::fragment<wmma::matrix_b, 16, 16, 16, half, wmma::col_major> b;
            wmma::load_matrix_sync(b, Vp + (size_t)(wx * 128 + j * 16) * Nd + k0, Nd);
            wmma::mma_sync(acc[j], a, b, acc[j]);
        }
    }

    // epilogue: two 16x64 chunks; split fp32 -> hi/lo fp16 (lossless) and store
    float* st = stg[warp];
#pragma unroll
    for (int ch = 0; ch < 2; ++ch) {
#pragma unroll
        for (int j = 0; j < 4; ++j)
            wmma::store_matrix_sync(st + j * 16, acc[ch * 4 + j], 68, wmma::mem_row_major);
        __syncwarp();
        const int r = lane & 15, cs = (lane >> 4) * 32;   // lane: row r, 32 cols at cs
        __align__(16) __half tH[32], tL[32];
#pragma unroll
        for (int c = 0; c < 32; ++c) {
            float v = st[r * 68 + cs + c];
            __half hh = __float2half_rn(v);
            tH[c] = hh;
            tL[c] = __float2half_rn(v - __half2float(hh));
        }
        size_t off = (size_t)(wy * 16 + r) * DVd + wx * 128 + ch * 64 + cs;
#pragma unroll
        for (int c = 0; c < 4; ++c) {
            ((uint4*)(KVh + off))[c] = ((const uint4*)tH)[c];
            ((uint4*)(KVl + off))[c] = ((const uint4*)tL)[c];
        }
        __syncwarp();
    }
}

// ---------------- attention O = 0.25 * kv^T Q, fused SFA -> oh fp16 -------------
// Loop t inside, membrane state in registers.
// Block tile 128(E) x 64(N), 8 warps (4x2), warp tile 32x32, K=64 direct-global.
__global__ void __launch_bounds__(256)
av_fused()
{
    __shared__ __align__(16) float stg[8][32 * 36];

    const int tid = threadIdx.x, warp = tid >> 5, lane = tid & 31;
    const int wy = warp >> 1, wx = warp & 1;
    const int zp = blockIdx.z;               // b*8 + h
    const int b = zp >> 3, hd = zp & 7;
    const int eBase = blockIdx.y * 128, nBase = blockIdx.x * 64;

    float* st = stg[warp];
    const int eRow = eBase + wy * 32 + lane;

    float hreg[32];
#pragma unroll
    for (int c = 0; c < 32; ++c) hreg[c] = 0.f;

    for (int t = 0; t < Td; ++t) {
        const int tb = t * Bd + b;
        const size_t zkv = (size_t)(tb * NHd + hd) * DHd * DVd;
        const __half* KVh = g_kvhi + zkv;
        const __half* KVl = g_kvlo + zkv;
        const __half* Qp  = g_qh + ((size_t)tb * Cd + hd * DHd) * Nd;

        wmma::fragment<wmma::accumulator, 16, 16, 16, float> acc[2][2];
#pragma unroll
        for (int i = 0; i < 2; ++i)
#pragma unroll
            for (int j = 0; j < 2; ++j) wmma::fill_fragment(acc[i][j], 0.f);

#pragma unroll
        for (int k0 = 0; k0 < DHd; k0 += 16) {
            wmma::fragment<wmma::matrix_a, 16, 16, 16, half, wmma::col_major> ah[2], al[2];
#pragma unroll
            for (int i = 0; i < 2; ++i) {
                wmma::load_matrix_sync(ah[i], KVh + (size_t)k0 * DVd + eBase + wy * 32 + i * 16, DVd);
                wmma::load_matrix_sync(al[i], KVl + (size_t)k0 * DVd + eBase + wy * 32 + i * 16, DVd);
            }
#pragma unroll
            for (int j = 0; j < 2; ++j) {
                wmma::fragment<wmma::matrix_b, 16, 16, 16, half, wmma::row_major> bf;
                wmma::load_matrix_sync(bf, Qp + (size_t)k0 * Nd + nBase + wx * 32 + j * 16, Nd);
#pragma unroll
                for (int i = 0; i < 2; ++i) {
                    wmma::mma_sync(acc[i][j], ah[i], bf, acc[i][j]);
                    wmma::mma_sync(acc[i][j], al[i], bf, acc[i][j]);
                }
            }
        }

#pragma unroll
        for (int i = 0; i < 2; ++i)
#pragma unroll
            for (int j = 0; j < 2; ++j)
                wmma::store_matrix_sync(st + (i * 16) * 36 + j * 16, acc[i][j], 36,
                                        wmma::mem_row_major);
        __syncwarp();

        __align__(16) __half tmp[32];
#pragma unroll
        for (int c = 0; c < 32; ++c) {
            float u = hreg[c] + st[lane * 36 + c] * 0.25f;
            float s = rintf(fminf(fmaxf(u, 0.f), 8.f));
            hreg[c] = u - s;
            tmp[c] = __float2half_rn(s * 0.125f);
        }
        __half* yp = g_oh + ((size_t)tb * CVd + hd * DVd + eRow) * Nd + nBase + wx * 32;
#pragma unroll
        for (int c = 0; c < 4; ++c) ((uint4*)yp)[c] = ((const uint4*)tmp)[c];
        __syncwarp();
    }
}

// ---------------- launch --------------------------------------------------------
extern "C" void kernel_launch(void* const* d_in, const int* in_sizes, int n_in,
                              void* d_out, int out_size)
{
    (void)in_sizes; (void)n_in; (void)out_size;

    const float* x       = (const float*)d_in[0];
    const float* wq      = (const float*)d_in[1];
    const float* wk      = (const float*)d_in[2];
    const float* wv      = (const float*)d_in[3];
    const float* wp      = (const float*)d_in[4];
    const float* q_scale = (const float*)d_in[5];
    const float* q_bias  = (const float*)d_in[6];
    const float* k_scale = (const float*)d_in[7];
    const float* k_bias  = (const float*)d_in[8];
    const float* v_scale = (const float*)d_in[9];
    const float* v_bias  = (const float*)d_in[10];
    const float* p_scale = (const float*)d_in[11];
    const float* p_bias  = (const float*)d_in[12];
    float* out = (float*)d_out;

    void* p;
    cudaGetSymbolAddress(&p, g_xs);    __half* xs  = (__half*)p;
    cudaGetSymbolAddress(&p, g_qh);    __half* qh  = (__half*)p;
    cudaGetSymbolAddress(&p, g_kh);    __half* kh  = (__half*)p;
    cudaGetSymbolAddress(&p, g_vh);    __half* vh  = (__half*)p;
    cudaGetSymbolAddress(&p, g_oh);    __half* oh  = (__half*)p;
    cudaGetSymbolAddress(&p, g_wq_hi); __half* wqh = (__half*)p;
    cudaGetSymbolAddress(&p, g_wq_lo); __half* wql = (__half*)p;
    cudaGetSymbolAddress(&p, g_wk_hi); __half* wkh = (__half*)p;
    cudaGetSymbolAddress(&p, g_wk_lo); __half* wkl = (__half*)p;
    cudaGetSymbolAddress(&p, g_wv_hi); __half* wvh = (__half*)p;
    cudaGetSymbolAddress(&p, g_wv_lo); __half* wvl = (__half*)p;
    cudaGetSymbolAddress(&p, g_wp_hi); __half* wph = (__half*)p;
    cudaGetSymbolAddress(&p, g_wp_lo); __half* wpl = (__half*)p;

    const int perT1 = Bd * Cd * Nd;   // 4,194,304

    // 0. weight folding + hi/lo split
    prep_w<<<(Cd  * Cd  + 255) / 256, 256>>>(wq, q_scale, wqh, wql, Cd,  Cd);
    prep_w<<<(Cd  * Cd  + 255) / 256, 256>>>(wk, k_scale, wkh, wkl, Cd,  Cd);
    prep_w<<<(CVd * Cd  + 255) / 256, 256>>>(wv, v_scale, wvh, wvl, CVd, Cd);
    prep_w<<<(Cd  * CVd + 255) / 256, 256>>>(wp, p_scale, wph, wpl, Cd,  CVd);

    // 1. head spikes (fp16)
    sfa_f2h<<<perT1 / 256, 256>>>(x, xs, perT1);

    // 2. q/k/v conv + BN + SFA fused (tensor cores)
    conv_fused<true><<<dim3(4,  4, Bd), 256>>>(wqh, wql, xs, q_bias, qh, Cd,  Cd);
    conv_fused<true><<<dim3(4,  4, Bd), 256>>>(wkh, wkl, xs, k_bias, kh, Cd,  Cd);
    conv_fused<true><<<dim3(4, 16, Bd), 256>>>(wvh, wvl, xs, v_bias, vh, CVd, Cd);

    // 3. kv = K V^T with fused hi/lo split
    kv_wmma<<<Zd, 256>>>();

    // 4. O = 0.25 * kv^T Q with fused SFA
    av_fused<<<dim3(4, 2, Bd * NHd), 256>>>();

    // 5. projection conv + BN -> fp32 output
    conv_fused<false><<<dim3(4, 4, Bd), 256>>>(wph, wpl, oh, p_bias, out, Cd, CVd);
}

// round 6
// speedup vs baseline: 2.2073x; 2.2073x over previous
#include <cuda_runtime.h>
#include <cuda_fp16.h>
#include <cuda_pipeline.h>
#include <mma.h>
#include <cstdint>

using namespace nvcuda;

// Problem dims (fixed)
#define Td  4
#define Bd  32
#define Cd  512
#define CVd 2048
#define Nd  256
#define NHd 8
#define DHd 64
#define DVd 256
#define TBd (Td*Bd)      // 128
#define Zd  (TBd*NHd)    // 1024

// ---------------- static scratch ------------------------------------------------
__device__ __half g_xs [(size_t)TBd*Cd *Nd];
__device__ float  g_qf [(size_t)TBd*Cd *Nd];
__device__ float  g_kf [(size_t)TBd*Cd *Nd];
__device__ float  g_vf [(size_t)TBd*CVd*Nd];
__device__ __half g_qh [(size_t)TBd*Cd *Nd];
__device__ __half g_kh [(size_t)TBd*Cd *Nd];
__device__ __half g_vh [(size_t)TBd*CVd*Nd];
__device__ float  g_kv [(size_t)Zd*DHd*DVd];
__device__ __half g_kvhi[(size_t)Zd*DHd*DVd];
__device__ __half g_kvlo[(size_t)Zd*DHd*DVd];
__device__ float  g_of [(size_t)TBd*CVd*Nd];
__device__ __half g_oh [(size_t)TBd*CVd*Nd];
__device__ __half g_wq_hi[Cd*Cd],  g_wq_lo[Cd*Cd];
__device__ __half g_wk_hi[Cd*Cd],  g_wk_lo[Cd*Cd];
__device__ __half g_wv_hi[CVd*Cd], g_wv_lo[CVd*Cd];
__device__ __half g_wp_hi[Cd*CVd], g_wp_lo[Cd*CVd];
__device__ float g_b2d_q[Cd*128], g_b2d_k[Cd*128], g_b2d_v[CVd*128], g_b2d_p[Cd*128];

// ---------------- prep kernels --------------------------------------------------
__global__ void prep_w(const float* __restrict__ w, const float* __restrict__ scale,
                       __half* __restrict__ hi, __half* __restrict__ lo, int M, int K)
{
    int i = blockIdx.x * blockDim.x + threadIdx.x;
    if (i >= M * K) return;
    float v = w[i] * scale[i / K];
    __half h = __float2half_rn(v);
    hi[i] = h;
    lo[i] = __float2half_rn(v - __half2float(h));
}

__global__ void prep_b(const float* __restrict__ bias, float* __restrict__ b2d, int M)
{
    int i = blockIdx.x * blockDim.x + threadIdx.x;
    if (i >= M * 128) return;
    b2d[i] = bias[i >> 7];
}

// ---------------- SFA scan: fp32 in -> fp16 spikes out --------------------------
__global__ void sfa_f2h(const float* __restrict__ in, __half* __restrict__ out, int perT)
{
    int i = blockIdx.x * blockDim.x + threadIdx.x;
    if (i >= perT) return;
    float h = 0.f;
#pragma unroll
    for (int t = 0; t < Td; ++t) {
        float u = h + in[(size_t)t * perT + i];
        float s = rintf(fminf(fmaxf(u, 0.f), 8.f));   // round-half-to-even
        h = u - s;
        out[(size_t)t * perT + i] = __float2half_rn(s * 0.125f);
    }
}

// ---------------- conv GEMM: 3-stage cp.async pipeline, wmma --------------------
// Y[z][m][n] = (Whi+Wlo)[m][k] * B[z][k][n] + bias[m]
// Block tile 128x128, BK=32, 8 warps (4x2), warp tile 32x64.
// Per-stage smem: Ah 128x40h (10240B) + Al 128x40h (10240B) + B 32x136h (8704B)
static constexpr int STAGES = 3;
static constexpr int ST_SZ  = 29184;                 // bytes per stage
static constexpr int OFF_AL = 10240;
static constexpr int OFF_B  = 20480;
static constexpr int SM_DYN = STAGES * ST_SZ;        // 87552 B

__global__ void __launch_bounds__(256)
conv_wmma(const __half* __restrict__ Ahi, const __half* __restrict__ Alo,
          const __half* __restrict__ Ball, const float* __restrict__ b2d,
          float* __restrict__ Yall, int M, int K)
{
    extern __shared__ __align__(16) unsigned char sm[];

    const int tid = threadIdx.x;
    const int warp = tid >> 5;
    const int wy = warp >> 1, wx = warp & 1;
    const int mBase = blockIdx.y * 128, nBase = blockIdx.x * 128;

    const __half* B = Ball + (size_t)blockIdx.z * K * Nd;
    float*        Y = Yall + (size_t)blockIdx.z * M * Nd;

    // loader indices
    const int ar = tid >> 1, ac = (tid & 1) * 16;    // A: 128 rows x 32 k
    const int br = tid >> 3, bc = (tid & 7) * 16;    // B: 32 k x 128 n

    auto load_stage = [&](int s, int kb) {
        __half* ah = (__half*)(sm + s * ST_SZ);
        __half* al = (__half*)(sm + s * ST_SZ + OFF_AL);
        __half* bb = (__half*)(sm + s * ST_SZ + OFF_B);
        const __half* gh = Ahi + (size_t)(mBase + ar) * K + kb + ac;
        const __half* gl = Alo + (size_t)(mBase + ar) * K + kb + ac;
        __pipeline_memcpy_async(ah + ar * 40 + ac,     gh,     16);
        __pipeline_memcpy_async(ah + ar * 40 + ac + 8, gh + 8, 16);
        __pipeline_memcpy_async(al + ar * 40 + ac,     gl,     16);
        __pipeline_memcpy_async(al + ar * 40 + ac + 8, gl + 8, 16);
        const __half* gb = B + (size_t)(kb + br) * Nd + nBase + bc;
        __pipeline_memcpy_async(bb + br * 136 + bc,     gb,     16);
        __pipeline_memcpy_async(bb + br * 136 + bc + 8, gb + 8, 16);
    };

    wmma::fragment<wmma::accumulator, 16, 16, 16, float> acc[2][4];
#pragma unroll
    for (int i = 0; i < 2; ++i)
#pragma unroll
        for (int j = 0; j < 4; ++j)
            wmma::load_matrix_sync(acc[i][j],
                b2d + (size_t)(mBase + wy * 32 + i * 16) * 128 + wx * 64 + j * 16,
                128, wmma::mem_row_major);

    // prefill stages 0..STAGES-2 with chunks kb=0,32
#pragma unroll
    for (int i = 0; i < STAGES - 1; ++i) {
        load_stage(i, i * 32);
        __pipeline_commit();
    }

    int rs = 0;   // read stage: chunk kb lives in stage (kb/32) % STAGES
    for (int kb = 0; kb < K; kb += 32) {
        __pipeline_wait_prior(STAGES - 2);
        __syncthreads();   // all warps past previous compute; stage ws reusable

        // issue next chunk BEFORE compute: ws = (rs + STAGES-1) % STAGES
        int nk = kb + (STAGES - 1) * 32;
        if (nk < K) {
            int ws = rs + (STAGES - 1); if (ws >= STAGES) ws -= STAGES;
            load_stage(ws, nk);
        }
        __pipeline_commit();

        const __half* ahp = (const __half*)(sm + rs * ST_SZ);
        const __half* alp = (const __half*)(sm + rs * ST_SZ + OFF_AL);
        const __half* bbp = (const __half*)(sm + rs * ST_SZ + OFF_B);
#pragma unroll
        for (int kk = 0; kk < 32; kk += 16) {
            wmma::fragment<wmma::matrix_a, 16, 16, 16, half, wmma::row_major> ah[2], al[2];
#pragma unroll
            for (int i = 0; i < 2; ++i) {
                wmma::load_matrix_sync(ah[i], ahp + (wy * 32 + i * 16) * 40 + kk, 40);
                wmma::load_matrix_sync(al[i], alp + (wy * 32 + i * 16) * 40 + kk, 40);
            }
#pragma unroll
            for (int j = 0; j < 4; ++j) {
                wmma::fragment<wmma::matrix_b, 16, 16, 16, half, wmma::row_major> bf;
                wmma::load_matrix_sync(bf, bbp + kk * 136 + wx * 64 + j * 16, 136);
#pragma unroll
                for (int i = 0; i < 2; ++i) {
                    wmma::mma_sync(acc[i][j], ah[i], bf, acc[i][j]);
                    wmma::mma_sync(acc[i][j], al[i], bf, acc[i][j]);
                }
            }
        }

        rs = rs + 1; if (rs == STAGES) rs = 0;
    }

#pragma unroll
    for (int i = 0; i < 2; ++i)
#pragma unroll
        for (int j = 0; j < 4; ++j)
            wmma::store_matrix_sync(
                Y + (size_t)(mBase + wy * 32 + i * 16) * Nd + nBase + wx * 64 + j * 16,
                acc[i][j], Nd, wmma::mem_row_major);
}

// ---------------- attention phase 1: kv[d][e] = sum_n K[d,n] V[e,n] -------------
__global__ void __launch_bounds__(256)
kv_wmma()
{
    const int tid = threadIdx.x, warp = tid >> 5;
    const int wy = warp >> 1, wx = warp & 1;
    const int z = blockIdx.x;
    const int tb = z >> 3, h = z & 7;

    const __half* Kp = g_kh + ((size_t)tb * Cd  + h * DHd) * Nd;
    const __half* Vp = g_vh + ((size_t)tb * CVd + h * DVd) * Nd;
    float*        KV = g_kv + (size_t)z * DHd * DVd;

    wmma::fragment<wmma::accumulator, 16, 16, 16, float> acc[8];
#pragma unroll
    for (int j = 0; j < 8; ++j) wmma::fill_fragment(acc[j], 0.f);

    for (int k0 = 0; k0 < Nd; k0 += 16) {
        wmma::fragment<wmma::matrix_a, 16, 16, 16, half, wmma::row_major> a;
        wmma::load_matrix_sync(a, Kp + (size_t)(wy * 16) * Nd + k0, Nd);
#pragma unroll
        for (int j = 0; j < 8; ++j) {
            wmma::fragment<wmma::matrix_b, 16, 16, 16, half, wmma::col_major> b;
            wmma::load_matrix_sync(b, Vp + (size_t)(wx * 128 + j * 16) * Nd + k0, Nd);
            wmma::mma_sync(acc[j], a, b, acc[j]);
        }
    }
#pragma unroll
    for (int j = 0; j < 8; ++j)
        wmma::store_matrix_sync(KV + (size_t)(wy * 16) * DVd + wx * 128 + j * 16,
                                acc[j], DVd, wmma::mem_row_major);
}

// ---------------- kv lossless hi/lo split ---------------------------------------
__global__ void kv_split(int n)
{
    int i = blockIdx.x * blockDim.x + threadIdx.x;
    if (i >= n) return;
    float v = g_kv[i];
    __half h = __float2half_rn(v);
    g_kvhi[i] = h;
    g_kvlo[i] = __float2half_rn(v - __half2float(h));
}

// ---------------- attention phase 2: O[e][n] = 0.25 * sum_d kv[d][e] Q[d,n] -----
__global__ void __launch_bounds__(256, 2)
av_wmma()
{
    const int tid = threadIdx.x, warp = tid >> 5;
    const int wy = warp >> 1, wx = warp & 1;
    const int z = blockIdx.z;
    const int tb = z >> 3, h = z & 7;
    const int eBase = blockIdx.y * 128, nBase = blockIdx.x * 128;

    const __half* KVh = g_kvhi + (size_t)z * DHd * DVd;
    const __half* KVl = g_kvlo + (size_t)z * DHd * DVd;
    const __half* Qp  = g_qh + ((size_t)tb * Cd  + h * DHd) * Nd;
    float*        O   = g_of + ((size_t)tb * CVd + h * DVd) * Nd;

    wmma::fragment<wmma::accumulator, 16, 16, 16, float> acc[2][4];
#pragma unroll
    for (int i = 0; i < 2; ++i)
#pragma unroll
        for (int j = 0; j < 4; ++j) wmma::fill_fragment(acc[i][j], 0.f);

    for (int k0 = 0; k0 < DHd; k0 += 16) {
        wmma::fragment<wmma::matrix_a, 16, 16, 16, half, wmma::col_major> ah[2], al[2];
#pragma unroll
        for (int i = 0; i < 2; ++i) {
            wmma::load_matrix_sync(ah[i], KVh + (eBase + wy * 32 + i * 16) + (size_t)k0 * DVd, DVd);
            wmma::load_matrix_sync(al[i], KVl + (eBase + wy * 32 + i * 16) + (size_t)k0 * DVd, DVd);
        }
#pragma unroll
        for (int j = 0; j < 4; ++j) {
            wmma::fragment<wmma::matrix_b, 16, 16, 16, half, wmma::row_major> b;
            wmma::load_matrix_sync(b, Qp + (size_t)k0 * Nd + nBase + wx * 64 + j * 16, Nd);
#pragma unroll
            for (int i = 0; i < 2; ++i) {
                wmma::mma_sync(acc[i][j], ah[i], b, acc[i][j]);
                wmma::mma_sync(acc[i][j], al[i], b, acc[i][j]);
            }
        }
    }
#pragma unroll
    for (int i = 0; i < 2; ++i)
#pragma unroll
        for (int j = 0; j < 4; ++j) {
#pragma unroll
            for (int e = 0; e < acc[i][j].num_elements; ++e) acc[i][j].x[e] *= 0.25f;
            wmma::store_matrix_sync(
                O + (size_t)(eBase + wy * 32 + i * 16) * Nd + nBase + wx * 64 + j * 16,
                acc[i][j], Nd, wmma::mem_row_major);
        }
}

// ---------------- launch --------------------------------------------------------
extern "C" void kernel_launch(void* const* d_in, const int* in_sizes, int n_in,
                              void* d_out, int out_size)
{
    (void)in_sizes; (void)n_in; (void)out_size;

    const float* x       = (const float*)d_in[0];
    const float* wq      = (const float*)d_in[1];
    const float* wk      = (const float*)d_in[2];
    const float* wv      = (const float*)d_in[3];
    const float* wp      = (const float*)d_in[4];
    const float* q_scale = (const float*)d_in[5];
    const float* q_bias  = (const float*)d_in[6];
    const float* k_scale = (const float*)d_in[7];
    const float* k_bias  = (const float*)d_in[8];
    const float* v_scale = (const float*)d_in[9];
    const float* v_bias  = (const float*)d_in[10];
    const float* p_scale = (const float*)d_in[11];
    const float* p_bias  = (const float*)d_in[12];
    float* out = (float*)d_out;

    void* p;
    cudaGetSymbolAddress(&p, g_xs);    __half* xs   = (__half*)p;
    cudaGetSymbolAddress(&p, g_qf);    float*  qf   = (float*)p;
    cudaGetSymbolAddress(&p, g_kf);    float*  kf   = (float*)p;
    cudaGetSymbolAddress(&p, g_vf);    float*  vf   = (float*)p;
    cudaGetSymbolAddress(&p, g_qh);    __half* qh   = (__half*)p;
    cudaGetSymbolAddress(&p, g_kh);    __half* kh   = (__half*)p;
    cudaGetSymbolAddress(&p, g_vh);    __half* vh   = (__half*)p;
    cudaGetSymbolAddress(&p, g_of);    float*  of   = (float*)p;
    cudaGetSymbolAddress(&p, g_oh);    __half* oh   = (__half*)p;
    cudaGetSymbolAddress(&p, g_wq_hi); __half* wqh  = (__half*)p;
    cudaGetSymbolAddress(&p, g_wq_lo); __half* wql  = (__half*)p;
    cudaGetSymbolAddress(&p, g_wk_hi); __half* wkh  = (__half*)p;
    cudaGetSymbolAddress(&p, g_wk_lo); __half* wkl  = (__half*)p;
    cudaGetSymbolAddress(&p, g_wv_hi); __half* wvh  = (__half*)p;
    cudaGetSymbolAddress(&p, g_wv_lo); __half* wvl  = (__half*)p;
    cudaGetSymbolAddress(&p, g_wp_hi); __half* wph  = (__half*)p;
    cudaGetSymbolAddress(&p, g_wp_lo); __half* wpl  = (__half*)p;
    cudaGetSymbolAddress(&p, g_b2d_q); float*  b2q  = (float*)p;
    cudaGetSymbolAddress(&p, g_b2d_k); float*  b2k  = (float*)p;
    cudaGetSymbolAddress(&p, g_b2d_v); float*  b2v  = (float*)p;
    cudaGetSymbolAddress(&p, g_b2d_p); float*  b2p  = (float*)p;

    cudaFuncSetAttribute(conv_wmma, cudaFuncAttributeMaxDynamicSharedMemorySize, SM_DYN);

    const int perT1 = Bd * Cd  * Nd;   //  4,194,304
    const int perTv = Bd * CVd * Nd;   // 16,777,216

    // 0. weight folding + split, bias broadcast tables
    prep_w<<<(Cd  * Cd  + 255) / 256, 256>>>(wq, q_scale, wqh, wql, Cd,  Cd);
    prep_w<<<(Cd  * Cd  + 255) / 256, 256>>>(wk, k_scale, wkh, wkl, Cd,  Cd);
    prep_w<<<(CVd * Cd  + 255) / 256, 256>>>(wv, v_scale, wvh, wvl, CVd, Cd);
    prep_w<<<(Cd  * CVd + 255) / 256, 256>>>(wp, p_scale, wph, wpl, Cd,  CVd);
    prep_b<<<(Cd  * 128 + 255) / 256, 256>>>(q_bias, b2q, Cd);
    prep_b<<<(Cd  * 128 + 255) / 256, 256>>>(k_bias, b2k, Cd);
    prep_b<<<(CVd * 128 + 255) / 256, 256>>>(v_bias, b2v, CVd);
    prep_b<<<(Cd  * 128 + 255) / 256, 256>>>(p_bias, b2p, Cd);

    // 1. head spikes (fp16)
    sfa_f2h<<<perT1 / 256, 256>>>(x, xs, perT1);

    // 2. q/k/v conv + BN (pipelined tensor-core GEMM)
    conv_wmma<<<dim3(2,  4, TBd), 256, SM_DYN>>>(wqh, wql, xs, b2q, qf, Cd,  Cd);
    conv_wmma<<<dim3(2,  4, TBd), 256, SM_DYN>>>(wkh, wkl, xs, b2k, kf, Cd,  Cd);
    conv_wmma<<<dim3(2, 16, TBd), 256, SM_DYN>>>(wvh, wvl, xs, b2v, vf, CVd, Cd);

    // 3. spike q/k/v (fp16)
    sfa_f2h<<<perT1 / 256, 256>>>(qf, qh, perT1);
    sfa_f2h<<<perT1 / 256, 256>>>(kf, kh, perT1);
    sfa_f2h<<<perTv / 256, 256>>>(vf, vh, perTv);

    // 4. linear attention (exact): O = 0.25 * Q^T (K V^T)
    kv_wmma<<<Zd, 256>>>();
    kv_split<<<(Zd * DHd * DVd + 255) / 256, 256>>>(Zd * DHd * DVd);
    av_wmma<<<dim3(2, 2, Zd), 256>>>();

    // 5. attn spikes (fp16)
    sfa_f2h<<<perTv / 256, 256>>>(of, oh, perTv);

    // 6. projection conv + BN -> output (fp32)
    conv_wmma<<<dim3(2, 4, TBd), 256, SM_DYN>>>(wph, wpl, oh, b2p, out, Cd, CVd);
}

// round 8
// speedup vs baseline: 2.2277x; 1.0093x over previous
#include <cuda_runtime.h>
#include <cuda_fp16.h>
#include <cuda_pipeline.h>
#include <mma.h>
#include <cstdint>

using namespace nvcuda;

// Problem dims (fixed)
#define Td  4
#define Bd  32
#define Cd  512
#define CVd 2048
#define Nd  256
#define NHd 8
#define DHd 64
#define DVd 256
#define TBd (Td*Bd)      // 128
#define Zd  (TBd*NHd)    // 1024

// ---------------- static scratch ------------------------------------------------
__device__ __half g_xs [(size_t)TBd*Cd *Nd];
__device__ float  g_qf [(size_t)TBd*Cd *Nd];
__device__ float  g_kf [(size_t)TBd*Cd *Nd];
__device__ float  g_vf [(size_t)TBd*CVd*Nd];
__device__ __half g_qh [(size_t)TBd*Cd *Nd];
__device__ __half g_kh [(size_t)TBd*Cd *Nd];
__device__ __half g_vh [(size_t)TBd*CVd*Nd];
__device__ __half g_kvhi[(size_t)Zd*DHd*DVd];
__device__ __half g_kvlo[(size_t)Zd*DHd*DVd];
__device__ __half g_oh [(size_t)TBd*CVd*Nd];    // attn spikes [z][e][n]
__device__ __half g_wq_hi[Cd*Cd],  g_wq_lo[Cd*Cd];
__device__ __half g_wk_hi[Cd*Cd],  g_wk_lo[Cd*Cd];
__device__ __half g_wv_hi[CVd*Cd], g_wv_lo[CVd*Cd];
__device__ __half g_wp_hi[Cd*CVd], g_wp_lo[Cd*CVd];
__device__ float g_b2d_q[Cd*128], g_b2d_k[Cd*128], g_b2d_v[CVd*128], g_b2d_p[Cd*128];

// ---------------- prep kernels --------------------------------------------------
__global__ void prep_w(const float* __restrict__ w, const float* __restrict__ scale,
                       __half* __restrict__ hi, __half* __restrict__ lo, int M, int K)
{
    int i = blockIdx.x * blockDim.x + threadIdx.x;
    if (i >= M * K) return;
    float v = w[i] * scale[i / K];
    __half h = __float2half_rn(v);
    hi[i] = h;
    lo[i] = __float2half_rn(v - __half2float(h));
}

__global__ void prep_b(const float* __restrict__ bias, float* __restrict__ b2d, int M)
{
    int i = blockIdx.x * blockDim.x + threadIdx.x;
    if (i >= M * 128) return;
    b2d[i] = bias[i >> 7];
}

// ---------------- SFA scan, vectorized x4: fp32 -> fp16 spikes ------------------
__global__ void sfa_f2h4(const float4* __restrict__ in, uint2* __restrict__ out, int perT4)
{
    int i = blockIdx.x * blockDim.x + threadIdx.x;
    if (i >= perT4) return;
    float h0 = 0.f, h1 = 0.f, h2 = 0.f, h3 = 0.f;
#pragma unroll
    for (int t = 0; t < Td; ++t) {
        float4 v = in[(size_t)t * perT4 + i];
        float u0 = h0 + v.x, u1 = h1 + v.y, u2 = h2 + v.z, u3 = h3 + v.w;
        float s0 = rintf(fminf(fmaxf(u0, 0.f), 8.f));
        float s1 = rintf(fminf(fmaxf(u1, 0.f), 8.f));
        float s2 = rintf(fminf(fmaxf(u2, 0.f), 8.f));
        float s3 = rintf(fminf(fmaxf(u3, 0.f), 8.f));
        h0 = u0 - s0; h1 = u1 - s1; h2 = u2 - s2; h3 = u3 - s3;
        __half2 lo = __floats2half2_rn(s0 * 0.125f, s1 * 0.125f);   // exact
        __half2 hi = __floats2half2_rn(s2 * 0.125f, s3 * 0.125f);
        uint2 o;
        o.x = *(const unsigned*)&lo;
        o.y = *(const unsigned*)&hi;
        out[(size_t)t * perT4 + i] = o;
    }
}

// ---------------- conv GEMM: 3-stage cp.async pipeline, wmma (R6, unchanged) ----
static constexpr int STAGES = 3;
static constexpr int ST_SZ  = 29184;
static constexpr int OFF_AL = 10240;
static constexpr int OFF_B  = 20480;
static constexpr int SM_DYN = STAGES * ST_SZ;        // 87552 B

__global__ void __launch_bounds__(256)
conv_wmma(const __half* __restrict__ Ahi, const __half* __restrict__ Alo,
          const __half* __restrict__ Ball, const float* __restrict__ b2d,
          float* __restrict__ Yall, int M, int K)
{
    extern __shared__ __align__(16) unsigned char sm[];

    const int tid = threadIdx.x;
    const int warp = tid >> 5;
    const int wy = warp >> 1, wx = warp & 1;
    const int mBase = blockIdx.y * 128, nBase = blockIdx.x * 128;

    const __half* B = Ball + (size_t)blockIdx.z * K * Nd;
    float*        Y = Yall + (size_t)blockIdx.z * M * Nd;

    const int ar = tid >> 1, ac = (tid & 1) * 16;
    const int br = tid >> 3, bc = (tid & 7) * 16;

    auto load_stage = [&](int s, int kb) {
        __half* ah = (__half*)(sm + s * ST_SZ);
        __half* al = (__half*)(sm + s * ST_SZ + OFF_AL);
        __half* bb = (__half*)(sm + s * ST_SZ + OFF_B);
        const __half* gh = Ahi + (size_t)(mBase + ar) * K + kb + ac;
        const __half* gl = Alo + (size_t)(mBase + ar) * K + kb + ac;
        __pipeline_memcpy_async(ah + ar * 40 + ac,     gh,     16);
        __pipeline_memcpy_async(ah + ar * 40 + ac + 8, gh + 8, 16);
        __pipeline_memcpy_async(al + ar * 40 + ac,     gl,     16);
        __pipeline_memcpy_async(al + ar * 40 + ac + 8, gl + 8, 16);
        const __half* gb = B + (size_t)(kb + br) * Nd + nBase + bc;
        __pipeline_memcpy_async(bb + br * 136 + bc,     gb,     16);
        __pipeline_memcpy_async(bb + br * 136 + bc + 8, gb + 8, 16);
    };

    wmma::fragment<wmma::accumulator, 16, 16, 16, float> acc[2][4];
#pragma unroll
    for (int i = 0; i < 2; ++i)
#pragma unroll
        for (int j = 0; j < 4; ++j)
            wmma::load_matrix_sync(acc[i][j],
                b2d + (size_t)(mBase + wy * 32 + i * 16) * 128 + wx * 64 + j * 16,
                128, wmma::mem_row_major);

#pragma unroll
    for (int i = 0; i < STAGES - 1; ++i) {
        load_stage(i, i * 32);
        __pipeline_commit();
    }

    int rs = 0;
    for (int kb = 0; kb < K; kb += 32) {
        __pipeline_wait_prior(STAGES - 2);
        __syncthreads();

        int nk = kb + (STAGES - 1) * 32;
        if (nk < K) {
            int ws = rs + (STAGES - 1); if (ws >= STAGES) ws -= STAGES;
            load_stage(ws, nk);
        }
        __pipeline_commit();

        const __half* ahp = (const __half*)(sm + rs * ST_SZ);
        const __half* alp = (const __half*)(sm + rs * ST_SZ + OFF_AL);
        const __half* bbp = (const __half*)(sm + rs * ST_SZ + OFF_B);
#pragma unroll
        for (int kk = 0; kk < 32; kk += 16) {
            wmma::fragment<wmma::matrix_a, 16, 16, 16, half, wmma::row_major> ah[2], al[2];
#pragma unroll
            for (int i = 0; i < 2; ++i) {
                wmma::load_matrix_sync(ah[i], ahp + (wy * 32 + i * 16) * 40 + kk, 40);
                wmma::load_matrix_sync(al[i], alp + (wy * 32 + i * 16) * 40 + kk, 40);
            }
#pragma unroll
            for (int j = 0; j < 4; ++j) {
                wmma::fragment<wmma::matrix_b, 16, 16, 16, half, wmma::row_major> bf;
                wmma::load_matrix_sync(bf, bbp + kk * 136 + wx * 64 + j * 16, 136);
#pragma unroll
                for (int i = 0; i < 2; ++i) {
                    wmma::mma_sync(acc[i][j], ah[i], bf, acc[i][j]);
                    wmma::mma_sync(acc[i][j], al[i], bf, acc[i][j]);
                }
            }
        }

        rs = rs + 1; if (rs == STAGES) rs = 0;
    }

#pragma unroll
    for (int i = 0; i < 2; ++i)
#pragma unroll
        for (int j = 0; j < 4; ++j)
            wmma::store_matrix_sync(
                Y + (size_t)(mBase + wy * 32 + i * 16) * Nd + nBase + wx * 64 + j * 16,
                acc[i][j], Nd, wmma::mem_row_major);
}

// ---------------- kv = K V^T with fused lossless hi/lo split (R4 epilogue) ------
__global__ void __launch_bounds__(256)
kv_wmma()
{
    __shared__ __align__(16) float stg[8][16 * 68];

    const int tid = threadIdx.x, warp = tid >> 5, lane = tid & 31;
    const int wy = warp >> 1, wx = warp & 1;
    const int z = blockIdx.x;
    const int tb = z >> 3, h = z & 7;

    const __half* Kp = g_kh + ((size_t)tb * Cd  + h * DHd) * Nd;
    const __half* Vp = g_vh + ((size_t)tb * CVd + h * DVd) * Nd;
    __half* KVh = g_kvhi + (size_t)z * DHd * DVd;
    __half* KVl = g_kvlo + (size_t)z * DHd * DVd;

    wmma::fragment<wmma::accumulator, 16, 16, 16, float> acc[8];
#pragma unroll
    for (int j = 0; j < 8; ++j) wmma::fill_fragment(acc[j], 0.f);

    for (int k0 = 0; k0 < Nd; k0 += 16) {
        wmma::fragment<wmma::matrix_a, 16, 16, 16, half, wmma::row_major> a;
        wmma::load_matrix_sync(a, Kp + (size_t)(wy * 16) * Nd + k0, Nd);
#pragma unroll
        for (int j = 0; j < 8; ++j) {
            wmma::fragment<wmma::matrix_b, 16, 16, 16, half, wmma::col_major> b;
            wmma::load_matrix_sync(b, Vp + (size_t)(wx * 128 + j * 16) * Nd + k0, Nd);
            wmma::mma_sync(acc[j], a, b, acc[j]);
        }
    }

    float* st = stg[warp];
#pragma unroll
    for (int ch = 0; ch < 2; ++ch) {
#pragma unroll
        for (int j = 0; j < 4; ++j)
            wmma::store_matrix_sync(st + j * 16, acc[ch * 4 + j], 68, wmma::mem_row_major);
        __syncwarp();
        const int r = lane & 15, cs = (lane >> 4) * 32;
        __align__(16) __half tH[32], tL[32];
#pragma unroll
        for (int c = 0; c < 32; ++c) {
            float v = st[r * 68 + cs + c];
            __half hh = __float2half_rn(v);
            tH[c] = hh;
            tL[c] = __float2half_rn(v - __half2float(hh));   // lossless
        }
        size_t off = (size_t)(wy * 16 + r) * DVd + wx * 128 + ch * 64 + cs;
#pragma unroll
        for (int c = 0; c < 4; ++c) {
            ((uint4*)(KVh + off))[c] = ((const uint4*)tH)[c];
            ((uint4*)(KVl + off))[c] = ((const uint4*)tL)[c];
        }
        __syncwarp();
    }
}

// ---------------- attention O = 0.25 * kv^T Q, fused SFA -> oh (R4, ldm=36) -----
// Loop t inside, membrane state in registers. Block tile 128(E) x 64(N).
__global__ void __launch_bounds__(256)
av_fused()
{
    __shared__ __align__(16) float stg[8][32 * 36];

    const int tid = threadIdx.x, warp = tid >> 5, lane = tid & 31;
    const int wy = warp >> 1, wx = warp & 1;
    const int zp = blockIdx.z;               // b*8 + h
    const int b = zp >> 3, hd = zp & 7;
    const int eBase = blockIdx.y * 128, nBase = blockIdx.x * 64;

    float* st = stg[warp];
    const int eRow = eBase + wy * 32 + lane;

    float hreg[32];
#pragma unroll
    for (int c = 0; c < 32; ++c) hreg[c] = 0.f;

    for (int t = 0; t < Td; ++t) {
        const int tb = t * Bd + b;
        const size_t zkv = (size_t)(tb * NHd + hd) * DHd * DVd;
        const __half* KVh = g_kvhi + zkv;
        const __half* KVl = g_kvlo + zkv;
        const __half* Qp  = g_qh + ((size_t)tb * Cd + hd * DHd) * Nd;

        wmma::fragment<wmma::accumulator, 16, 16, 16, float> acc[2][2];
#pragma unroll
        for (int i = 0; i < 2; ++i)
#pragma unroll
            for (int j = 0; j < 2; ++j) wmma::fill_fragment(acc[i][j], 0.f);

#pragma unroll
        for (int k0 = 0; k0 < DHd; k0 += 16) {
            wmma::fragment<wmma::matrix_a, 16, 16, 16, half, wmma::col_major> ah[2], al[2];
#pragma unroll
            for (int i = 0; i < 2; ++i) {
                wmma::load_matrix_sync(ah[i], KVh + (size_t)k0 * DVd + eBase + wy * 32 + i * 16, DVd);
                wmma::load_matrix_sync(al[i], KVl + (size_t)k0 * DVd + eBase + wy * 32 + i * 16, DVd);
            }
#pragma unroll
            for (int j = 0; j < 2; ++j) {
                wmma::fragment<wmma::matrix_b, 16, 16, 16, half, wmma::row_major> bf;
                wmma::load_matrix_sync(bf, Qp + (size_t)k0 * Nd + nBase + wx * 32 + j * 16, Nd);
#pragma unroll
                for (int i = 0; i < 2; ++i) {
                    wmma::mma_sync(acc[i][j], ah[i], bf, acc[i][j]);
                    wmma::mma_sync(acc[i][j], al[i], bf, acc[i][j]);
                }
            }
        }

#pragma unroll
        for (int i = 0; i < 2; ++i)
#pragma unroll
            for (int j = 0; j < 2; ++j)
                wmma::store_matrix_sync(st + (i * 16) * 36 + j * 16, acc[i][j], 36,
                                        wmma::mem_row_major);
        __syncwarp();

        __align__(16) __half tmp[32];
#pragma unroll
        for (int c = 0; c < 32; ++c) {
            float u = hreg[c] + st[lane * 36 + c] * 0.25f;
            float s = rintf(fminf(fmaxf(u, 0.f), 8.f));
            hreg[c] = u - s;
            tmp[c] = __float2half_rn(s * 0.125f);
        }
        __half* yp = g_oh + ((size_t)tb * CVd + hd * DVd + eRow) * Nd + nBase + wx * 32;
#pragma unroll
        for (int c = 0; c < 4; ++c) ((uint4*)yp)[c] = ((const uint4*)tmp)[c];
        __syncwarp();
    }
}

// ---------------- launch --------------------------------------------------------
extern "C" void kernel_launch(void* const* d_in, const int* in_sizes, int n_in,
                              void* d_out, int out_size)
{
    (void)in_sizes; (void)n_in; (void)out_size;

    const float* x       = (const float*)d_in[0];
    const float* wq      = (const float*)d_in[1];
    const float* wk      = (const float*)d_in[2];
    const float* wv      = (const float*)d_in[3];
    const float* wp      = (const float*)d_in[4];
    const float* q_scale = (const float*)d_in[5];
    const float* q_bias  = (const float*)d_in[6];
    const float* k_scale = (const float*)d_in[7];
    const float* k_bias  = (const float*)d_in[8];
    const float* v_scale = (const float*)d_in[9];
    const float* v_bias  = (const float*)d_in[10];
    const float* p_scale = (const float*)d_in[11];
    const float* p_bias  = (const float*)d_in[12];
    float* out = (float*)d_out;

    void* p;
    cudaGetSymbolAddress(&p, g_xs);    __half* xs   = (__half*)p;
    cudaGetSymbolAddress(&p, g_qf);    float*  qf   = (float*)p;
    cudaGetSymbolAddress(&p, g_kf);    float*  kf   = (float*)p;
    cudaGetSymbolAddress(&p, g_vf);    float*  vf   = (float*)p;
    cudaGetSymbolAddress(&p, g_qh);    __half* qh   = (__half*)p;
    cudaGetSymbolAddress(&p, g_kh);    __half* kh   = (__half*)p;
    cudaGetSymbolAddress(&p, g_vh);    __half* vh   = (__half*)p;
    cudaGetSymbolAddress(&p, g_oh);    __half* oh   = (__half*)p;
    cudaGetSymbolAddress(&p, g_wq_hi); __half* wqh  = (__half*)p;
    cudaGetSymbolAddress(&p, g_wq_lo); __half* wql  = (__half*)p;
    cudaGetSymbolAddress(&p, g_wk_hi); __half* wkh  = (__half*)p;
    cudaGetSymbolAddress(&p, g_wk_lo); __half* wkl  = (__half*)p;
    cudaGetSymbolAddress(&p, g_wv_hi); __half* wvh  = (__half*)p;
    cudaGetSymbolAddress(&p, g_wv_lo); __half* wvl  = (__half*)p;
    cudaGetSymbolAddress(&p, g_wp_hi); __half* wph  = (__half*)p;
    cudaGetSymbolAddress(&p, g_wp_lo); __half* wpl  = (__half*)p;
    cudaGetSymbolAddress(&p, g_b2d_q); float*  b2q  = (float*)p;
    cudaGetSymbolAddress(&p, g_b2d_k); float*  b2k  = (float*)p;
    cudaGetSymbolAddress(&p, g_b2d_v); float*  b2v  = (float*)p;
    cudaGetSymbolAddress(&p, g_b2d_p); float*  b2p  = (float*)p;

    cudaFuncSetAttribute(conv_wmma, cudaFuncAttributeMaxDynamicSharedMemorySize, SM_DYN);

    const int perT1 = Bd * Cd  * Nd;   //  4,194,304
    const int perTv = Bd * CVd * Nd;   // 16,777,216

    // 0. weight folding + split, bias broadcast tables
    prep_w<<<(Cd  * Cd  + 255) / 256, 256>>>(wq, q_scale, wqh, wql, Cd,  Cd);
    prep_w<<<(Cd  * Cd  + 255) / 256, 256>>>(wk, k_scale, wkh, wkl, Cd,  Cd);
    prep_w<<<(CVd * Cd  + 255) / 256, 256>>>(wv, v_scale, wvh, wvl, CVd, Cd);
    prep_w<<<(Cd  * CVd + 255) / 256, 256>>>(wp, p_scale, wph, wpl, Cd,  CVd);
    prep_b<<<(Cd  * 128 + 255) / 256, 256>>>(q_bias, b2q, Cd);
    prep_b<<<(Cd  * 128 + 255) / 256, 256>>>(k_bias, b2k, Cd);
    prep_b<<<(CVd * 128 + 255) / 256, 256>>>(v_bias, b2v, CVd);
    prep_b<<<(Cd  * 128 + 255) / 256, 256>>>(p_bias, b2p, Cd);

    // 1. head spikes (fp16), vectorized
    sfa_f2h4<<<perT1 / 4 / 256, 256>>>((const float4*)x, (uint2*)xs, perT1 / 4);

    // 2. q/k/v conv + BN (pipelined tensor-core GEMM)
    conv_wmma<<<dim3(2,  4, TBd), 256, SM_DYN>>>(wqh, wql, xs, b2q, qf, Cd,  Cd);
    conv_wmma<<<dim3(2,  4, TBd), 256, SM_DYN>>>(wkh, wkl, xs, b2k, kf, Cd,  Cd);
    conv_wmma<<<dim3(2, 16, TBd), 256, SM_DYN>>>(wvh, wvl, xs, b2v, vf, CVd, Cd);

    // 3. spike q/k/v (fp16), vectorized
    sfa_f2h4<<<perT1 / 4 / 256, 256>>>((const float4*)qf, (uint2*)qh, perT1 / 4);
    sfa_f2h4<<<perT1 / 4 / 256, 256>>>((const float4*)kf, (uint2*)kh, perT1 / 4);
    sfa_f2h4<<<perTv / 4 / 256, 256>>>((const float4*)vf, (uint2*)vh, perTv / 4);

    // 4. linear attention: kv = K V^T (fused hi/lo split), O = 0.25 kv^T Q (fused SFA)
    kv_wmma<<<Zd, 256>>>();
    av_fused<<<dim3(4, 2, Bd * NHd), 256>>>();

    // 5. projection conv + BN -> fp32 output
    conv_wmma<<<dim3(2, 4, TBd), 256, SM_DYN>>>(wph, wpl, oh, b2p, out, Cd, CVd);
}

// round 9
// speedup vs baseline: 2.3796x; 1.0682x over previous
#include <cuda_runtime.h>
#include <cuda_fp16.h>
#include <cuda_pipeline.h>
#include <mma.h>
#include <cstdint>

using namespace nvcuda;

// Problem dims (fixed)
#define Td  4
#define Bd  32
#define Cd  512
#define CVd 2048
#define Nd  256
#define NHd 8
#define DHd 64
#define DVd 256
#define TBd (Td*Bd)      // 128
#define Zd  (TBd*NHd)    // 1024

// ---------------- static scratch ------------------------------------------------
__device__ __half g_xs [(size_t)TBd*Cd *Nd];
__device__ float  g_qf [(size_t)TBd*Cd *Nd];
__device__ float  g_kf [(size_t)TBd*Cd *Nd];
__device__ float  g_vf [(size_t)TBd*CVd*Nd];
__device__ __half g_qh [(size_t)TBd*Cd *Nd];
__device__ __half g_kh [(size_t)TBd*Cd *Nd];
__device__ __half g_vh [(size_t)TBd*CVd*Nd];
__device__ __half g_kvhi[(size_t)Zd*DHd*DVd];
__device__ __half g_kvlo[(size_t)Zd*DHd*DVd];
__device__ __half g_oh [(size_t)TBd*CVd*Nd];    // attn spikes [z][e][n]
__device__ __half g_wq_hi[Cd*Cd],  g_wq_lo[Cd*Cd];
__device__ __half g_wk_hi[Cd*Cd],  g_wk_lo[Cd*Cd];
__device__ __half g_wv_hi[CVd*Cd], g_wv_lo[CVd*Cd];
__device__ __half g_wp_hi[Cd*CVd], g_wp_lo[Cd*CVd];
__device__ float g_b2d_q[Cd*128], g_b2d_k[Cd*128], g_b2d_v[CVd*128], g_b2d_p[Cd*128];

// ---------------- prep kernels --------------------------------------------------
__global__ void prep_w(const float* __restrict__ w, const float* __restrict__ scale,
                       __half* __restrict__ hi, __half* __restrict__ lo, int M, int K)
{
    int i = blockIdx.x * blockDim.x + threadIdx.x;
    if (i >= M * K) return;
    float v = w[i] * scale[i / K];
    __half h = __float2half_rn(v);
    hi[i] = h;
    lo[i] = __float2half_rn(v - __half2float(h));
}

__global__ void prep_b(const float* __restrict__ bias, float* __restrict__ b2d, int M)
{
    int i = blockIdx.x * blockDim.x + threadIdx.x;
    if (i >= M * 128) return;
    b2d[i] = bias[i >> 7];
}

// ---------------- SFA scan, vectorized x4: fp32 -> fp16 spikes ------------------
__global__ void sfa_f2h4(const float4* __restrict__ in, uint2* __restrict__ out, int perT4)
{
    int i = blockIdx.x * blockDim.x + threadIdx.x;
    if (i >= perT4) return;
    float h0 = 0.f, h1 = 0.f, h2 = 0.f, h3 = 0.f;
#pragma unroll
    for (int t = 0; t < Td; ++t) {
        float4 v = in[(size_t)t * perT4 + i];
        float u0 = h0 + v.x, u1 = h1 + v.y, u2 = h2 + v.z, u3 = h3 + v.w;
        float s0 = rintf(fminf(fmaxf(u0, 0.f), 8.f));
        float s1 = rintf(fminf(fmaxf(u1, 0.f), 8.f));
        float s2 = rintf(fminf(fmaxf(u2, 0.f), 8.f));
        float s3 = rintf(fminf(fmaxf(u3, 0.f), 8.f));
        h0 = u0 - s0; h1 = u1 - s1; h2 = u2 - s2; h3 = u3 - s3;
        __half2 lo = __floats2half2_rn(s0 * 0.125f, s1 * 0.125f);
        __half2 hi = __floats2half2_rn(s2 * 0.125f, s3 * 0.125f);
        uint2 o;
        o.x = *(const unsigned*)&lo;
        o.y = *(const unsigned*)&hi;
        out[(size_t)t * perT4 + i] = o;
    }
}

// ---------------- conv GEMM (hi+lo): 3-stage cp.async, wmma (R8, unchanged) -----
static constexpr int STAGES = 3;
static constexpr int ST_SZ  = 29184;
static constexpr int OFF_AL = 10240;
static constexpr int OFF_B  = 20480;
static constexpr int SM_DYN = STAGES * ST_SZ;        // 87552 B

__global__ void __launch_bounds__(256)
conv_wmma(const __half* __restrict__ Ahi, const __half* __restrict__ Alo,
          const __half* __restrict__ Ball, const float* __restrict__ b2d,
          float* __restrict__ Yall, int M, int K)
{
    extern __shared__ __align__(16) unsigned char sm[];

    const int tid = threadIdx.x;
    const int warp = tid >> 5;
    const int wy = warp >> 1, wx = warp & 1;
    const int mBase = blockIdx.y * 128, nBase = blockIdx.x * 128;

    const __half* B = Ball + (size_t)blockIdx.z * K * Nd;
    float*        Y = Yall + (size_t)blockIdx.z * M * Nd;

    const int ar = tid >> 1, ac = (tid & 1) * 16;
    const int br = tid >> 3, bc = (tid & 7) * 16;

    auto load_stage = [&](int s, int kb) {
        __half* ah = (__half*)(sm + s * ST_SZ);
        __half* al = (__half*)(sm + s * ST_SZ + OFF_AL);
        __half* bb = (__half*)(sm + s * ST_SZ + OFF_B);
        const __half* gh = Ahi + (size_t)(mBase + ar) * K + kb + ac;
        const __half* gl = Alo + (size_t)(mBase + ar) * K + kb + ac;
        __pipeline_memcpy_async(ah + ar * 40 + ac,     gh,     16);
        __pipeline_memcpy_async(ah + ar * 40 + ac + 8, gh + 8, 16);
        __pipeline_memcpy_async(al + ar * 40 + ac,     gl,     16);
        __pipeline_memcpy_async(al + ar * 40 + ac + 8, gl + 8, 16);
        const __half* gb = B + (size_t)(kb + br) * Nd + nBase + bc;
        __pipeline_memcpy_async(bb + br * 136 + bc,     gb,     16);
        __pipeline_memcpy_async(bb + br * 136 + bc + 8, gb + 8, 16);
    };

    wmma::fragment<wmma::accumulator, 16, 16, 16, float> acc[2][4];
#pragma unroll
    for (int i = 0; i < 2; ++i)
#pragma unroll
        for (int j = 0; j < 4; ++j)
            wmma::load_matrix_sync(acc[i][j],
                b2d + (size_t)(mBase + wy * 32 + i * 16) * 128 + wx * 64 + j * 16,
                128, wmma::mem_row_major);

#pragma unroll
    for (int i = 0; i < STAGES - 1; ++i) {
        load_stage(i, i * 32);
        __pipeline_commit();
    }

    int rs = 0;
    for (int kb = 0; kb < K; kb += 32) {
        __pipeline_wait_prior(STAGES - 2);
        __syncthreads();

        int nk = kb + (STAGES - 1) * 32;
        if (nk < K) {
            int ws = rs + (STAGES - 1); if (ws >= STAGES) ws -= STAGES;
            load_stage(ws, nk);
        }
        __pipeline_commit();

        const __half* ahp = (const __half*)(sm + rs * ST_SZ);
        const __half* alp = (const __half*)(sm + rs * ST_SZ + OFF_AL);
        const __half* bbp = (const __half*)(sm + rs * ST_SZ + OFF_B);
#pragma unroll
        for (int kk = 0; kk < 32; kk += 16) {
            wmma::fragment<wmma::matrix_a, 16, 16, 16, half, wmma::row_major> ah[2], al[2];
#pragma unroll
            for (int i = 0; i < 2; ++i) {
                wmma::load_matrix_sync(ah[i], ahp + (wy * 32 + i * 16) * 40 + kk, 40);
                wmma::load_matrix_sync(al[i], alp + (wy * 32 + i * 16) * 40 + kk, 40);
            }
#pragma unroll
            for (int j = 0; j < 4; ++j) {
                wmma::fragment<wmma::matrix_b, 16, 16, 16, half, wmma::row_major> bf;
                wmma::load_matrix_sync(bf, bbp + kk * 136 + wx * 64 + j * 16, 136);
#pragma unroll
                for (int i = 0; i < 2; ++i) {
                    wmma::mma_sync(acc[i][j], ah[i], bf, acc[i][j]);
                    wmma::mma_sync(acc[i][j], al[i], bf, acc[i][j]);
                }
            }
        }

        rs = rs + 1; if (rs == STAGES) rs = 0;
    }

#pragma unroll
    for (int i = 0; i < 2; ++i)
#pragma unroll
        for (int j = 0; j < 4; ++j)
            wmma::store_matrix_sync(
                Y + (size_t)(mBase + wy * 32 + i * 16) * Nd + nBase + wx * 64 + j * 16,
                acc[i][j], Nd, wmma::mem_row_major);
}

// ---------------- conv GEMM single-term (p conv): BK=64, 2-stage cp.async -------
// Y = W[m][k] * B[z][k][n] + bias.  No lo term (output feeds nothing quantized).
static constexpr int P_OFF_B = 18432;                // A: 128x72 halves
static constexpr int P_ST    = 35840;                // + B: 64x136 halves
static constexpr int P_SMEM  = 2 * P_ST;             // 71680 B -> 2 CTAs/SM

__global__ void __launch_bounds__(256)
conv_wmma1(const __half* __restrict__ A, const __half* __restrict__ Ball,
           const float* __restrict__ b2d, float* __restrict__ Yall, int M, int K)
{
    extern __shared__ __align__(16) unsigned char sm[];

    const int tid = threadIdx.x;
    const int warp = tid >> 5;
    const int wy = warp >> 1, wx = warp & 1;
    const int mBase = blockIdx.y * 128, nBase = blockIdx.x * 128;

    const __half* B = Ball + (size_t)blockIdx.z * K * Nd;
    float*        Y = Yall + (size_t)blockIdx.z * M * Nd;

    const int ar = tid >> 1, ac = (tid & 1) * 32;    // A: 128 rows x 64 k
    const int br = tid >> 2, bc = (tid & 3) * 32;    // B: 64 k x 128 n

    auto load_stage = [&](int s, int kb) {
        __half* ah = (__half*)(sm + s * P_ST);
        __half* bb = (__half*)(sm + s * P_ST + P_OFF_B);
        const __half* ga = A + (size_t)(mBase + ar) * K + kb + ac;
#pragma unroll
        for (int q = 0; q < 4; ++q)
            __pipeline_memcpy_async(ah + ar * 72 + ac + q * 8, ga + q * 8, 16);
        const __half* gb = B + (size_t)(kb + br) * Nd + nBase + bc;
#pragma unroll
        for (int q = 0; q < 4; ++q)
            __pipeline_memcpy_async(bb + br * 136 + bc + q * 8, gb + q * 8, 16);
    };

    wmma::fragment<wmma::accumulator, 16, 16, 16, float> acc[2][4];
#pragma unroll
    for (int i = 0; i < 2; ++i)
#pragma unroll
        for (int j = 0; j < 4; ++j)
            wmma::load_matrix_sync(acc[i][j],
                b2d + (size_t)(mBase + wy * 32 + i * 16) * 128 + wx * 64 + j * 16,
                128, wmma::mem_row_major);

    load_stage(0, 0);
    __pipeline_commit();

    int rs = 0;
    for (int kb = 0; kb < K; kb += 64) {
        __pipeline_wait_prior(0);    // chunk kb landed
        __syncthreads();             // all warps done with the other stage

        int nk = kb + 64;
        if (nk < K) load_stage(rs ^ 1, nk);
        __pipeline_commit();

        const __half* ahp = (const __half*)(sm + rs * P_ST);
        const __half* bbp = (const __half*)(sm + rs * P_ST + P_OFF_B);
#pragma unroll
        for (int kk = 0; kk < 64; kk += 16) {
            wmma::fragment<wmma::matrix_a, 16, 16, 16, half, wmma::row_major> ah[2];
#pragma unroll
            for (int i = 0; i < 2; ++i)
                wmma::load_matrix_sync(ah[i], ahp + (wy * 32 + i * 16) * 72 + kk, 72);
#pragma unroll
            for (int j = 0; j < 4; ++j) {
                wmma::fragment<wmma::matrix_b, 16, 16, 16, half, wmma::row_major> bf;
                wmma::load_matrix_sync(bf, bbp + kk * 136 + wx * 64 + j * 16, 136);
#pragma unroll
                for (int i = 0; i < 2; ++i)
                    wmma::mma_sync(acc[i][j], ah[i], bf, acc[i][j]);
            }
        }

        rs ^= 1;
    }

#pragma unroll
    for (int i = 0; i < 2; ++i)
#pragma unroll
        for (int j = 0; j < 4; ++j)
            wmma::store_matrix_sync(
                Y + (size_t)(mBase + wy * 32 + i * 16) * Nd + nBase + wx * 64 + j * 16,
                acc[i][j], Nd, wmma::mem_row_major);
}

// ---------------- kv = K V^T with fused lossless hi/lo split --------------------
__global__ void __launch_bounds__(256)
kv_wmma()
{
    __shared__ __align__(16) float stg[8][16 * 68];

    const int tid = threadIdx.x, warp = tid >> 5, lane = tid & 31;
    const int wy = warp >> 1, wx = warp & 1;
    const int z = blockIdx.x;
    const int tb = z >> 3, h = z & 7;

    const __half* Kp = g_kh + ((size_t)tb * Cd  + h * DHd) * Nd;
    const __half* Vp = g_vh + ((size_t)tb * CVd + h * DVd) * Nd;
    __half* KVh = g_kvhi + (size_t)z * DHd * DVd;
    __half* KVl = g_kvlo + (size_t)z * DHd * DVd;

    wmma::fragment<wmma::accumulator, 16, 16, 16, float> acc[8];
#pragma unroll
    for (int j = 0; j < 8; ++j) wmma::fill_fragment(acc[j], 0.f);

    for (int k0 = 0; k0 < Nd; k0 += 16) {
        wmma::fragment<wmma::matrix_a, 16, 16, 16, half, wmma::row_major> a;
        wmma::load_matrix_sync(a, Kp + (size_t)(wy * 16) * Nd + k0, Nd);
#pragma unroll
        for (int j = 0; j < 8; ++j) {
            wmma::fragment<wmma::matrix_b, 16, 16, 16, half, wmma::col_major> b;
            wmma::load_matrix_sync(b, Vp + (size_t)(wx * 128 + j * 16) * Nd + k0, Nd);
            wmma::mma_sync(acc[j], a, b, acc[j]);
        }
    }

    float* st = stg[warp];
#pragma unroll
    for (int ch = 0; ch < 2; ++ch) {
#pragma unroll
        for (int j = 0; j < 4; ++j)
            wmma::store_matrix_sync(st + j * 16, acc[ch * 4 + j], 68, wmma::mem_row_major);
        __syncwarp();
        const int r = lane & 15, cs = (lane >> 4) * 32;
        __align__(16) __half tH[32], tL[32];
#pragma unroll
        for (int c = 0; c < 32; ++c) {
            float v = st[r * 68 + cs + c];
            __half hh = __float2half_rn(v);
            tH[c] = hh;
            tL[c] = __float2half_rn(v - __half2float(hh));
        }
        size_t off = (size_t)(wy * 16 + r) * DVd + wx * 128 + ch * 64 + cs;
#pragma unroll
        for (int c = 0; c < 4; ++c) {
            ((uint4*)(KVh + off))[c] = ((const uint4*)tH)[c];
            ((uint4*)(KVl + off))[c] = ((const uint4*)tL)[c];
        }
        __syncwarp();
    }
}

// ---------------- attention O = 0.25 * kv^T Q, fused SFA -> oh ------------------
__global__ void __launch_bounds__(256)
av_fused()
{
    __shared__ __align__(16) float stg[8][32 * 36];

    const int tid = threadIdx.x, warp = tid >> 5, lane = tid & 31;
    const int wy = warp >> 1, wx = warp & 1;
    const int zp = blockIdx.z;
    const int b = zp >> 3, hd = zp & 7;
    const int eBase = blockIdx.y * 128, nBase = blockIdx.x * 64;

    float* st = stg[warp];
    const int eRow = eBase + wy * 32 + lane;

    float hreg[32];
#pragma unroll
    for (int c = 0; c < 32; ++c) hreg[c] = 0.f;

    for (int t = 0; t < Td; ++t) {
        const int tb = t * Bd + b;
        const size_t zkv = (size_t)(tb * NHd + hd) * DHd * DVd;
        const __half* KVh = g_kvhi + zkv;
        const __half* KVl = g_kvlo + zkv;
        const __half* Qp  = g_qh + ((size_t)tb * Cd + hd * DHd) * Nd;

        wmma::fragment<wmma::accumulator, 16, 16, 16, float> acc[2][2];
#pragma unroll
        for (int i = 0; i < 2; ++i)
#pragma unroll
            for (int j = 0; j < 2; ++j) wmma::fill_fragment(acc[i][j], 0.f);

#pragma unroll
        for (int k0 = 0; k0 < DHd; k0 += 16) {
            wmma::fragment<wmma::matrix_a, 16, 16, 16, half, wmma::col_major> ah[2], al[2];
#pragma unroll
            for (int i = 0; i < 2; ++i) {
                wmma::load_matrix_sync(ah[i], KVh + (size_t)k0 * DVd + eBase + wy * 32 + i * 16, DVd);
                wmma::load_matrix_sync(al[i], KVl + (size_t)k0 * DVd + eBase + wy * 32 + i * 16, DVd);
            }
#pragma unroll
            for (int j = 0; j < 2; ++j) {
                wmma::fragment<wmma::matrix_b, 16, 16, 16, half, wmma::row_major> bf;
                wmma::load_matrix_sync(bf, Qp + (size_t)k0 * Nd + nBase + wx * 32 + j * 16, Nd);
#pragma unroll
                for (int i = 0; i < 2; ++i) {
                    wmma::mma_sync(acc[i][j], ah[i], bf, acc[i][j]);
                    wmma::mma_sync(acc[i][j], al[i], bf, acc[i][j]);
                }
            }
        }

#pragma unroll
        for (int i = 0; i < 2; ++i)
#pragma unroll
            for (int j = 0; j < 2; ++j)
                wmma::store_matrix_sync(st + (i * 16) * 36 + j * 16, acc[i][j], 36,
                                        wmma::mem_row_major);
        __syncwarp();

        __align__(16) __half tmp[32];
#pragma unroll
        for (int c = 0; c < 32; ++c) {
            float u = hreg[c] + st[lane * 36 + c] * 0.25f;
            float s = rintf(fminf(fmaxf(u, 0.f), 8.f));
            hreg[c] = u - s;
            tmp[c] = __float2half_rn(s * 0.125f);
        }
        __half* yp = g_oh + ((size_t)tb * CVd + hd * DVd + eRow) * Nd + nBase + wx * 32;
#pragma unroll
        for (int c = 0; c < 4; ++c) ((uint4*)yp)[c] = ((const uint4*)tmp)[c];
        __syncwarp();
    }
}

// ---------------- launch --------------------------------------------------------
extern "C" void kernel_launch(void* const* d_in, const int* in_sizes, int n_in,
                              void* d_out, int out_size)
{
    (void)in_sizes; (void)n_in; (void)out_size;

    const float* x       = (const float*)d_in[0];
    const float* wq      = (const float*)d_in[1];
    const float* wk      = (const float*)d_in[2];
    const float* wv      = (const float*)d_in[3];
    const float* wp      = (const float*)d_in[4];
    const float* q_scale = (const float*)d_in[5];
    const float* q_bias  = (const float*)d_in[6];
    const float* k_scale = (const float*)d_in[7];
    const float* k_bias  = (const float*)d_in[8];
    const float* v_scale = (const float*)d_in[9];
    const float* v_bias  = (const float*)d_in[10];
    const float* p_scale = (const float*)d_in[11];
    const float* p_bias  = (const float*)d_in[12];
    float* out = (float*)d_out;

    void* p;
    cudaGetSymbolAddress(&p, g_xs);    __half* xs   = (__half*)p;
    cudaGetSymbolAddress(&p, g_qf);    float*  qf   = (float*)p;
    cudaGetSymbolAddress(&p, g_kf);    float*  kf   = (float*)p;
    cudaGetSymbolAddress(&p, g_vf);    float*  vf   = (float*)p;
    cudaGetSymbolAddress(&p, g_qh);    __half* qh   = (__half*)p;
    cudaGetSymbolAddress(&p, g_kh);    __half* kh   = (__half*)p;
    cudaGetSymbolAddress(&p, g_vh);    __half* vh   = (__half*)p;
    cudaGetSymbolAddress(&p, g_oh);    __half* oh   = (__half*)p;
    cudaGetSymbolAddress(&p, g_wq_hi); __half* wqh  = (__half*)p;
    cudaGetSymbolAddress(&p, g_wq_lo); __half* wql  = (__half*)p;
    cudaGetSymbolAddress(&p, g_wk_hi); __half* wkh  = (__half*)p;
    cudaGetSymbolAddress(&p, g_wk_lo); __half* wkl  = (__half*)p;
    cudaGetSymbolAddress(&p, g_wv_hi); __half* wvh  = (__half*)p;
    cudaGetSymbolAddress(&p, g_wv_lo); __half* wvl  = (__half*)p;
    cudaGetSymbolAddress(&p, g_wp_hi); __half* wph  = (__half*)p;
    cudaGetSymbolAddress(&p, g_wp_lo); __half* wpl  = (__half*)p;
    cudaGetSymbolAddress(&p, g_b2d_q); float*  b2q  = (float*)p;
    cudaGetSymbolAddress(&p, g_b2d_k); float*  b2k  = (float*)p;
    cudaGetSymbolAddress(&p, g_b2d_v); float*  b2v  = (float*)p;
    cudaGetSymbolAddress(&p, g_b2d_p); float*  b2p  = (float*)p;

    cudaFuncSetAttribute(conv_wmma,  cudaFuncAttributeMaxDynamicSharedMemorySize, SM_DYN);
    cudaFuncSetAttribute(conv_wmma1, cudaFuncAttributeMaxDynamicSharedMemorySize, P_SMEM);

    const int perT1 = Bd * Cd  * Nd;   //  4,194,304
    const int perTv = Bd * CVd * Nd;   // 16,777,216

    // 0. weight folding + split, bias broadcast tables
    prep_w<<<(Cd  * Cd  + 255) / 256, 256>>>(wq, q_scale, wqh, wql, Cd,  Cd);
    prep_w<<<(Cd  * Cd  + 255) / 256, 256>>>(wk, k_scale, wkh, wkl, Cd,  Cd);
    prep_w<<<(CVd * Cd  + 255) / 256, 256>>>(wv, v_scale, wvh, wvl, CVd, Cd);
    prep_w<<<(Cd  * CVd + 255) / 256, 256>>>(wp, p_scale, wph, wpl, Cd,  CVd);
    prep_b<<<(Cd  * 128 + 255) / 256, 256>>>(q_bias, b2q, Cd);
    prep_b<<<(Cd  * 128 + 255) / 256, 256>>>(k_bias, b2k, Cd);
    prep_b<<<(CVd * 128 + 255) / 256, 256>>>(v_bias, b2v, CVd);
    prep_b<<<(Cd  * 128 + 255) / 256, 256>>>(p_bias, b2p, Cd);

    // 1. head spikes (fp16), vectorized
    sfa_f2h4<<<perT1 / 4 / 256, 256>>>((const float4*)x, (uint2*)xs, perT1 / 4);

    // 2. q/k/v conv + BN (hi/lo, pipelined wmma — unchanged from R8)
    conv_wmma<<<dim3(2,  4, TBd), 256, SM_DYN>>>(wqh, wql, xs, b2q, qf, Cd,  Cd);
    conv_wmma<<<dim3(2,  4, TBd), 256, SM_DYN>>>(wkh, wkl, xs, b2k, kf, Cd,  Cd);
    conv_wmma<<<dim3(2, 16, TBd), 256, SM_DYN>>>(wvh, wvl, xs, b2v, vf, CVd, Cd);

    // 3. spike q/k/v (fp16), vectorized
    sfa_f2h4<<<perT1 / 4 / 256, 256>>>((const float4*)qf, (uint2*)qh, perT1 / 4);
    sfa_f2h4<<<perT1 / 4 / 256, 256>>>((const float4*)kf, (uint2*)kh, perT1 / 4);
    sfa_f2h4<<<perTv / 4 / 256, 256>>>((const float4*)vf, (uint2*)vh, perTv / 4);

    // 4. linear attention: kv = K V^T (fused hi/lo split), O = 0.25 kv^T Q (fused SFA)
    kv_wmma<<<Zd, 256>>>();
    av_fused<<<dim3(4, 2, Bd * NHd), 256>>>();

    // 5. projection conv + BN -> fp32 output (single fp16 weight term, BK=64)
    conv_wmma1<<<dim3(2, 4, TBd), 256, P_SMEM>>>(wph, oh, b2p, out, Cd, CVd);
}